// round 16
// baseline (speedup 1.0000x reference)
#include <cuda_runtime.h>

#define N_ROWS   100000
#define NBINS    512
#define BATCH    8192
#define KNN      16
#define COL_BLKS 64
#define CS_ROWS  (BATCH / COL_BLKS)     // 128 rows per colsum CTA
#define THREADS  512
#define PAIR_BLKS (BATCH / 2)           // 4096 CTAs, 2 batch rows each
#define TOTAL_BLKS (PAIR_BLKS + COL_BLKS)
#define P_BLKS   16
#define STRIPS_PER_PCTA (COL_BLKS / P_BLKS)   // 4
#define WROWS_PER_PCTA  (BATCH / P_BLKS)      // 512

// Scratch (device allocs forbidden). Fully rewritten every launch.
__device__ float  g_wpart[BATCH];             // w[i] * sum_j add[i][j]
__device__ float  g_bpart[COL_BLKS * NBINS];  // per-strip column sums
__device__ float  g_cpart[P_BLKS * NBINS];    // per-partial-CTA col sums
__device__ double g_wsum2[P_BLKS];            // per-partial-CTA weighted sums

// ---------------------------------------------------------------------------
// Kernel A (PROVEN R13 shape, ~36us): fused grid, no cross-CTA sync.
//   bid < 64 : column-sum strip
//   bid >= 64: TWO batch rows; warp j gathers neighbor j of both rows ->
//              8 gather LDG.128 in flight per lane.
// ---------------------------------------------------------------------------
__global__ __launch_bounds__(THREADS) void main_kernel(
    const float* __restrict__ outputs,
    const float* __restrict__ y,
    const float* __restrict__ weights,
    float* __restrict__ out_boost)   // -> d_out + 3
{
    const int bid = blockIdx.x;
    const int tid = threadIdx.x;

    if (bid < COL_BLKS) {
        const float* p = outputs + (size_t)bid * CS_ROWS * NBINS + tid;
        float s = 0.f;
#pragma unroll
        for (int rb = 0; rb < CS_ROWS; rb += 8) {
            float t8[8];
#pragma unroll
            for (int r = 0; r < 8; r++) t8[r] = p[(size_t)(rb + r) * NBINS];
#pragma unroll
            for (int r = 0; r < 8; r++) s += t8[r];
        }
        g_bpart[bid * NBINS + tid] = s;
        return;
    }

    __shared__ float s_base0[NBINS];
    __shared__ float s_base1[NBINS];
    __shared__ float s_add0[KNN];
    __shared__ float s_add1[KNN];

    const int p    = bid - COL_BLKS;
    const int i0   = 2 * p;
    const int i1   = i0 + 1;
    const int warp = tid >> 5;
    const int lane = tid & 31;

    // Stage both base rows in SMEM (256 float4 total).
    {
        float4* s0 = reinterpret_cast<float4*>(s_base0);
        float4* s1 = reinterpret_cast<float4*>(s_base1);
        const float4* b0 = reinterpret_cast<const float4*>(outputs + (size_t)i0 * NBINS);
        const float4* b1 = reinterpret_cast<const float4*>(outputs + (size_t)i1 * NBINS);
        if (tid < 128)            s0[tid]       = b0[tid];
        else if (tid < 256)       s1[tid - 128] = b1[tid - 128];
    }

    // 8 independent gather LDG.128 per lane — all issued before the barrier.
    const int nn0 = (int)y[i0 * KNN + warp];
    const int nn1 = (int)y[i1 * KNN + warp];
    const float4* q0 = reinterpret_cast<const float4*>(outputs + (size_t)nn0 * NBINS);
    const float4* q1 = reinterpret_cast<const float4*>(outputs + (size_t)nn1 * NBINS);

    float4 a0 = q0[lane];
    float4 a1 = q0[32 + lane];
    float4 a2 = q0[64 + lane];
    float4 a3 = q0[96 + lane];
    float4 c0 = q1[lane];
    float4 c1 = q1[32 + lane];
    float4 c2 = q1[64 + lane];
    float4 c3 = q1[96 + lane];

    __syncthreads();   // base rows staged

    const float4* s0 = reinterpret_cast<const float4*>(s_base0);
    const float4* s1 = reinterpret_cast<const float4*>(s_base1);

    float ma, mb;
    {
        float4 b0 = s0[lane], b1 = s0[32 + lane], b2 = s0[64 + lane], b3 = s0[96 + lane];
        float m0 = fmaxf(fmaxf(b0.x + a0.x, b0.y + a0.y), fmaxf(b0.z + a0.z, b0.w + a0.w));
        float m1 = fmaxf(fmaxf(b1.x + a1.x, b1.y + a1.y), fmaxf(b1.z + a1.z, b1.w + a1.w));
        float m2 = fmaxf(fmaxf(b2.x + a2.x, b2.y + a2.y), fmaxf(b2.z + a2.z, b2.w + a2.w));
        float m3 = fmaxf(fmaxf(b3.x + a3.x, b3.y + a3.y), fmaxf(b3.z + a3.z, b3.w + a3.w));
        ma = fmaxf(fmaxf(m0, m1), fmaxf(m2, m3));
    }
    {
        float4 b0 = s1[lane], b1 = s1[32 + lane], b2 = s1[64 + lane], b3 = s1[96 + lane];
        float m0 = fmaxf(fmaxf(b0.x + c0.x, b0.y + c0.y), fmaxf(b0.z + c0.z, b0.w + c0.w));
        float m1 = fmaxf(fmaxf(b1.x + c1.x, b1.y + c1.y), fmaxf(b1.z + c1.z, b1.w + c1.w));
        float m2 = fmaxf(fmaxf(b2.x + c2.x, b2.y + c2.y), fmaxf(b2.z + c2.z, b2.w + c2.w));
        float m3 = fmaxf(fmaxf(b3.x + c3.x, b3.y + c3.y), fmaxf(b3.z + c3.z, b3.w + c3.w));
        mb = fmaxf(fmaxf(m0, m1), fmaxf(m2, m3));
    }

#pragma unroll
    for (int o = 16; o; o >>= 1) {
        ma = fmaxf(ma, __shfl_xor_sync(0xffffffffu, ma, o));
        mb = fmaxf(mb, __shfl_xor_sync(0xffffffffu, mb, o));
    }
    if (lane == 0) { s_add0[warp] = ma; s_add1[warp] = mb; }
    __syncthreads();

    if (tid == 0) {
        float sa = 0.f, sb = 0.f;
#pragma unroll
        for (int j = 0; j < KNN; j++) { sa += s_add0[j]; sb += s_add1[j]; }
        out_boost[i0] = fmaxf((2.0f - sa * (1.0f / KNN)) * 0.5f, 0.5f);
        out_boost[i1] = fmaxf((2.0f - sb * (1.0f / KNN)) * 0.5f, 0.5f);
        g_wpart[i0]   = sa * weights[i0];
        g_wpart[i1]   = sb * weights[i1];
    }
}

// ---------------------------------------------------------------------------
// Kernel B: 16-CTA partials. NO atomics, NO fences — stream order only.
//   CTA c: col partial over 4 strips -> g_cpart[c]; weighted-sum partial over
//   512 g_wpart entries -> g_wsum2[c].
// ---------------------------------------------------------------------------
__global__ __launch_bounds__(THREADS) void part_kernel()
{
    __shared__ double s_ws[16];

    const int c    = blockIdx.x;
    const int tid  = threadIdx.x;
    const int warp = tid >> 5;
    const int lane = tid & 31;

    // Col partial: thread t owns bin t over this CTA's 4 strips (coalesced).
    {
        float t4[STRIPS_PER_PCTA];
#pragma unroll
        for (int k = 0; k < STRIPS_PER_PCTA; k++)
            t4[k] = g_bpart[(c * STRIPS_PER_PCTA + k) * NBINS + tid];
        float s = (t4[0] + t4[1]) + (t4[2] + t4[3]);
        g_cpart[c * NBINS + tid] = s;
    }

    // Weighted-sum partial: one g_wpart entry per thread (coalesced).
    {
        double ws = (double)g_wpart[c * WROWS_PER_PCTA + tid];
#pragma unroll
        for (int o = 16; o; o >>= 1)
            ws += __shfl_xor_sync(0xffffffffu, ws, o);
        if (lane == 0) s_ws[warp] = ws;
        __syncthreads();
        if (tid == 0) {
            double t = 0.0;
#pragma unroll
            for (int w = 0; w < 16; w++) t += s_ws[w];
            g_wsum2[c] = t;
        }
    }
}

// ---------------------------------------------------------------------------
// Kernel C: 1-CTA combine (L2-hot: g_cpart/g_wsum2 just written).
// ---------------------------------------------------------------------------
__global__ __launch_bounds__(THREADS) void comb_kernel(float* __restrict__ d_out)
{
    __shared__ float s_mx[16];
    __shared__ float s_mn[16];

    const int tid  = threadIdx.x;
    const int warp = tid >> 5;
    const int lane = tid & 31;

    float col = 0.f;
    {
        float t16[P_BLKS];
#pragma unroll
        for (int b = 0; b < P_BLKS; b++) t16[b] = g_cpart[b * NBINS + tid];
#pragma unroll
        for (int b = 0; b < P_BLKS; b++) col += t16[b];
    }
    float mx = col, mn = col;
#pragma unroll
    for (int o = 16; o; o >>= 1) {
        mx = fmaxf(mx, __shfl_xor_sync(0xffffffffu, mx, o));
        mn = fminf(mn, __shfl_xor_sync(0xffffffffu, mn, o));
    }
    if (lane == 0) { s_mx[warp] = mx; s_mn[warp] = mn; }
    __syncthreads();

    if (warp == 0) {
        float fx = (lane < 16) ? s_mx[lane] : -1e30f;
        float fn = (lane < 16) ? s_mn[lane] :  1e30f;
#pragma unroll
        for (int o = 8; o; o >>= 1) {
            fx = fmaxf(fx, __shfl_xor_sync(0xffffffffu, fx, o));
            fn = fminf(fn, __shfl_xor_sync(0xffffffffu, fn, o));
        }
        if (lane == 0) {
            double ws = 0.0;
#pragma unroll
            for (int b = 0; b < P_BLKS; b++) ws += g_wsum2[b];

            float bspread  = fx - fn;
            float ratio    = bspread / ((float)N_ROWS / (float)NBINS);
            float add_mean = (float)(ws / (double)(BATCH * KNN));
            float d        = 2.0f - add_mean;
            d = d * d;
            d_out[0] = ratio + d;   // cost
            d_out[1] = d;           // diff
            d_out[2] = ratio;       // b / target_b
        }
    }
}

// ---------------------------------------------------------------------------
extern "C" void kernel_launch(void* const* d_in, const int* in_sizes, int n_in,
                              void* d_out, int out_size)
{
    const float* outputs = (const float*)d_in[0];  // (100000, 512) f32
    const float* y       = (const float*)d_in[1];  // (8192, 16)   f32 indices
    const float* weights = (const float*)d_in[2];  // (8192,)      f32
    float* out = (float*)d_out;                    // [cost, diff, ratio, boost(8192)]

    main_kernel<<<TOTAL_BLKS, THREADS>>>(outputs, y, weights, out + 3);
    part_kernel<<<P_BLKS, THREADS>>>();
    comb_kernel<<<1, THREADS>>>(out);
}

// round 17
// speedup vs baseline: 1.0007x; 1.0007x over previous
#include <cuda_runtime.h>

#define N_ROWS   100000
#define NBINS    512
#define BATCH    8192
#define KNN      16
#define COL_BLKS 64
#define CS_ROWS  (BATCH / COL_BLKS)     // 128 rows per colsum CTA
#define THREADS  512
#define ROWS_PER_CTA 3
#define PAIR_BLKS ((BATCH + ROWS_PER_CTA - 1) / ROWS_PER_CTA)   // 2731
#define TOTAL_BLKS (PAIR_BLKS + COL_BLKS)
#define P_BLKS   16
#define STRIPS_PER_PCTA (COL_BLKS / P_BLKS)   // 4
#define WROWS_PER_PCTA  (BATCH / P_BLKS)      // 512

// Scratch (device allocs forbidden). Fully rewritten every launch.
__device__ float  g_wpart[BATCH];             // w[i] * sum_j add[i][j]
__device__ float  g_bpart[COL_BLKS * NBINS];  // per-strip column sums
__device__ float  g_cpart[P_BLKS * NBINS];    // per-partial-CTA col sums
__device__ double g_wsum2[P_BLKS];            // per-partial-CTA weighted sums

// ---------------------------------------------------------------------------
// Kernel A: fused grid, no cross-CTA sync.
//   bid < 64 : column-sum strip
//   bid >= 64: THREE batch rows; warp j gathers neighbor j of all three ->
//              12 gather LDG.128 in flight per lane.
// ---------------------------------------------------------------------------
__global__ __launch_bounds__(THREADS) void main_kernel(
    const float* __restrict__ outputs,
    const float* __restrict__ y,
    const float* __restrict__ weights,
    float* __restrict__ out_boost)   // -> d_out + 3
{
    const int bid = blockIdx.x;
    const int tid = threadIdx.x;

    if (bid < COL_BLKS) {
        const float* p = outputs + (size_t)bid * CS_ROWS * NBINS + tid;
        float s = 0.f;
#pragma unroll
        for (int rb = 0; rb < CS_ROWS; rb += 8) {
            float t8[8];
#pragma unroll
            for (int r = 0; r < 8; r++) t8[r] = p[(size_t)(rb + r) * NBINS];
#pragma unroll
            for (int r = 0; r < 8; r++) s += t8[r];
        }
        g_bpart[bid * NBINS + tid] = s;
        return;
    }

    __shared__ float s_base[ROWS_PER_CTA][NBINS];
    __shared__ float s_add[ROWS_PER_CTA][KNN];

    const int p    = bid - COL_BLKS;
    const int i0   = ROWS_PER_CTA * p;
    const int i1   = i0 + 1;
    const int i2r  = i0 + 2;
    const bool v2  = (i2r < BATCH);
    const int i2   = v2 ? i2r : (BATCH - 1);   // clamp for loads only
    const int warp = tid >> 5;
    const int lane = tid & 31;

    // Stage the three base rows in SMEM (384 float4 total).
    {
        const float4* b0 = reinterpret_cast<const float4*>(outputs + (size_t)i0 * NBINS);
        const float4* b1 = reinterpret_cast<const float4*>(outputs + (size_t)i1 * NBINS);
        const float4* b2 = reinterpret_cast<const float4*>(outputs + (size_t)i2 * NBINS);
        if (tid < 128)       reinterpret_cast<float4*>(s_base[0])[tid]       = b0[tid];
        else if (tid < 256)  reinterpret_cast<float4*>(s_base[1])[tid - 128] = b1[tid - 128];
        else if (tid < 384)  reinterpret_cast<float4*>(s_base[2])[tid - 256] = b2[tid - 256];
    }

    // 12 independent gather LDG.128 per lane — all issued before the barrier.
    const int nn0 = (int)y[i0 * KNN + warp];
    const int nn1 = (int)y[i1 * KNN + warp];
    const int nn2 = (int)y[i2 * KNN + warp];
    const float4* q0 = reinterpret_cast<const float4*>(outputs + (size_t)nn0 * NBINS);
    const float4* q1 = reinterpret_cast<const float4*>(outputs + (size_t)nn1 * NBINS);
    const float4* q2 = reinterpret_cast<const float4*>(outputs + (size_t)nn2 * NBINS);

    float4 a0 = q0[lane], a1 = q0[32 + lane], a2 = q0[64 + lane], a3 = q0[96 + lane];
    float4 c0 = q1[lane], c1 = q1[32 + lane], c2 = q1[64 + lane], c3 = q1[96 + lane];
    float4 e0 = q2[lane], e1 = q2[32 + lane], e2 = q2[64 + lane], e3 = q2[96 + lane];

    __syncthreads();   // base rows staged

    float m[ROWS_PER_CTA];
    {
        const float4* s = reinterpret_cast<const float4*>(s_base[0]);
        float4 b0 = s[lane], b1 = s[32 + lane], b2 = s[64 + lane], b3 = s[96 + lane];
        float m0 = fmaxf(fmaxf(b0.x + a0.x, b0.y + a0.y), fmaxf(b0.z + a0.z, b0.w + a0.w));
        float m1 = fmaxf(fmaxf(b1.x + a1.x, b1.y + a1.y), fmaxf(b1.z + a1.z, b1.w + a1.w));
        float m2 = fmaxf(fmaxf(b2.x + a2.x, b2.y + a2.y), fmaxf(b2.z + a2.z, b2.w + a2.w));
        float m3 = fmaxf(fmaxf(b3.x + a3.x, b3.y + a3.y), fmaxf(b3.z + a3.z, b3.w + a3.w));
        m[0] = fmaxf(fmaxf(m0, m1), fmaxf(m2, m3));
    }
    {
        const float4* s = reinterpret_cast<const float4*>(s_base[1]);
        float4 b0 = s[lane], b1 = s[32 + lane], b2 = s[64 + lane], b3 = s[96 + lane];
        float m0 = fmaxf(fmaxf(b0.x + c0.x, b0.y + c0.y), fmaxf(b0.z + c0.z, b0.w + c0.w));
        float m1 = fmaxf(fmaxf(b1.x + c1.x, b1.y + c1.y), fmaxf(b1.z + c1.z, b1.w + c1.w));
        float m2 = fmaxf(fmaxf(b2.x + c2.x, b2.y + c2.y), fmaxf(b2.z + c2.z, b2.w + c2.w));
        float m3 = fmaxf(fmaxf(b3.x + c3.x, b3.y + c3.y), fmaxf(b3.z + c3.z, b3.w + c3.w));
        m[1] = fmaxf(fmaxf(m0, m1), fmaxf(m2, m3));
    }
    {
        const float4* s = reinterpret_cast<const float4*>(s_base[2]);
        float4 b0 = s[lane], b1 = s[32 + lane], b2 = s[64 + lane], b3 = s[96 + lane];
        float m0 = fmaxf(fmaxf(b0.x + e0.x, b0.y + e0.y), fmaxf(b0.z + e0.z, b0.w + e0.w));
        float m1 = fmaxf(fmaxf(b1.x + e1.x, b1.y + e1.y), fmaxf(b1.z + e1.z, b1.w + e1.w));
        float m2 = fmaxf(fmaxf(b2.x + e2.x, b2.y + e2.y), fmaxf(b2.z + e2.z, b2.w + e2.w));
        float m3 = fmaxf(fmaxf(b3.x + e3.x, b3.y + e3.y), fmaxf(b3.z + e3.z, b3.w + e3.w));
        m[2] = fmaxf(fmaxf(m0, m1), fmaxf(m2, m3));
    }

#pragma unroll
    for (int o = 16; o; o >>= 1) {
        m[0] = fmaxf(m[0], __shfl_xor_sync(0xffffffffu, m[0], o));
        m[1] = fmaxf(m[1], __shfl_xor_sync(0xffffffffu, m[1], o));
        m[2] = fmaxf(m[2], __shfl_xor_sync(0xffffffffu, m[2], o));
    }
    if (lane == 0) {
        s_add[0][warp] = m[0];
        s_add[1][warp] = m[1];
        s_add[2][warp] = m[2];
    }
    __syncthreads();

    if (tid == 0) {
        float s0 = 0.f, s1 = 0.f, s2 = 0.f;
#pragma unroll
        for (int j = 0; j < KNN; j++) {
            s0 += s_add[0][j]; s1 += s_add[1][j]; s2 += s_add[2][j];
        }
        out_boost[i0] = fmaxf((2.0f - s0 * (1.0f / KNN)) * 0.5f, 0.5f);
        out_boost[i1] = fmaxf((2.0f - s1 * (1.0f / KNN)) * 0.5f, 0.5f);
        g_wpart[i0]   = s0 * weights[i0];
        g_wpart[i1]   = s1 * weights[i1];
        if (v2) {
            out_boost[i2r] = fmaxf((2.0f - s2 * (1.0f / KNN)) * 0.5f, 0.5f);
            g_wpart[i2r]   = s2 * weights[i2r];
        }
    }
}

// ---------------------------------------------------------------------------
// Kernel B: 16-CTA partials. No atomics/fences — stream order only.
// ---------------------------------------------------------------------------
__global__ __launch_bounds__(THREADS) void part_kernel()
{
    __shared__ double s_ws[16];

    const int c    = blockIdx.x;
    const int tid  = threadIdx.x;
    const int warp = tid >> 5;
    const int lane = tid & 31;

    {
        float t4[STRIPS_PER_PCTA];
#pragma unroll
        for (int k = 0; k < STRIPS_PER_PCTA; k++)
            t4[k] = g_bpart[(c * STRIPS_PER_PCTA + k) * NBINS + tid];
        g_cpart[c * NBINS + tid] = (t4[0] + t4[1]) + (t4[2] + t4[3]);
    }

    {
        double ws = (double)g_wpart[c * WROWS_PER_PCTA + tid];
#pragma unroll
        for (int o = 16; o; o >>= 1)
            ws += __shfl_xor_sync(0xffffffffu, ws, o);
        if (lane == 0) s_ws[warp] = ws;
        __syncthreads();
        if (tid == 0) {
            double t = 0.0;
#pragma unroll
            for (int w = 0; w < 16; w++) t += s_ws[w];
            g_wsum2[c] = t;
        }
    }
}

// ---------------------------------------------------------------------------
// Kernel C: 1-CTA combine (L2-hot partials).
// ---------------------------------------------------------------------------
__global__ __launch_bounds__(THREADS) void comb_kernel(float* __restrict__ d_out)
{
    __shared__ float s_mx[16];
    __shared__ float s_mn[16];

    const int tid  = threadIdx.x;
    const int warp = tid >> 5;
    const int lane = tid & 31;

    float col = 0.f;
    {
        float t16[P_BLKS];
#pragma unroll
        for (int b = 0; b < P_BLKS; b++) t16[b] = g_cpart[b * NBINS + tid];
#pragma unroll
        for (int b = 0; b < P_BLKS; b++) col += t16[b];
    }
    float mx = col, mn = col;
#pragma unroll
    for (int o = 16; o; o >>= 1) {
        mx = fmaxf(mx, __shfl_xor_sync(0xffffffffu, mx, o));
        mn = fminf(mn, __shfl_xor_sync(0xffffffffu, mn, o));
    }
    if (lane == 0) { s_mx[warp] = mx; s_mn[warp] = mn; }
    __syncthreads();

    if (warp == 0) {
        float fx = (lane < 16) ? s_mx[lane] : -1e30f;
        float fn = (lane < 16) ? s_mn[lane] :  1e30f;
#pragma unroll
        for (int o = 8; o; o >>= 1) {
            fx = fmaxf(fx, __shfl_xor_sync(0xffffffffu, fx, o));
            fn = fminf(fn, __shfl_xor_sync(0xffffffffu, fn, o));
        }
        if (lane == 0) {
            double ws = 0.0;
#pragma unroll
            for (int b = 0; b < P_BLKS; b++) ws += g_wsum2[b];

            float bspread  = fx - fn;
            float ratio    = bspread / ((float)N_ROWS / (float)NBINS);
            float add_mean = (float)(ws / (double)(BATCH * KNN));
            float d        = 2.0f - add_mean;
            d = d * d;
            d_out[0] = ratio + d;   // cost
            d_out[1] = d;           // diff
            d_out[2] = ratio;       // b / target_b
        }
    }
}

// ---------------------------------------------------------------------------
extern "C" void kernel_launch(void* const* d_in, const int* in_sizes, int n_in,
                              void* d_out, int out_size)
{
    const float* outputs = (const float*)d_in[0];  // (100000, 512) f32
    const float* y       = (const float*)d_in[1];  // (8192, 16)   f32 indices
    const float* weights = (const float*)d_in[2];  // (8192,)      f32
    float* out = (float*)d_out;                    // [cost, diff, ratio, boost(8192)]

    main_kernel<<<TOTAL_BLKS, THREADS>>>(outputs, y, weights, out + 3);
    part_kernel<<<P_BLKS, THREADS>>>();
    comb_kernel<<<1, THREADS>>>(out);
}